// round 14
// baseline (speedup 1.0000x reference)
#include <cuda_runtime.h>
#include <cuda_fp16.h>
#include <math.h>

#define B  32
#define S  2048
#define D  64
#define R  4
#define NB 32

#define LOG2E_F 1.4426950408889634f
#define LN2_F   0.69314718055994531f

// ---------------- scratch (device globals; no allocation) ----------------
__device__ int    g_bucket[B*R*S];            // 1 MB
__device__ int    g_sortidx[B*R*S];           // 1 MB
__device__ float  g_qninv[B*S];               // 256 KB
__device__ __half g_qh[(size_t)B*S*D];        // 8 MB   fp16 copy of query
__device__ __half g_vh[(size_t)B*S*D];        // 8 MB   fp16 copy of value
__device__ __half g_att[(size_t)B*S*R*D];     // 32 MB  [b][t][r][d]
__device__ float  g_lse[B*S*R];               // 1 MB   [b][t][r]

// ---------------- mma / cp.async / ldmatrix helpers ----------------------
__device__ __forceinline__ void mma_f16(float* c, const unsigned* a,
                                        unsigned b0, unsigned b1)
{
    asm volatile(
        "mma.sync.aligned.m16n8k16.row.col.f32.f16.f16.f32 "
        "{%0,%1,%2,%3}, {%4,%5,%6,%7}, {%8,%9}, {%0,%1,%2,%3};"
        : "+f"(c[0]), "+f"(c[1]), "+f"(c[2]), "+f"(c[3])
        : "r"(a[0]), "r"(a[1]), "r"(a[2]), "r"(a[3]), "r"(b0), "r"(b1));
}

__device__ __forceinline__ void ldsm4(unsigned& r0, unsigned& r1,
                                      unsigned& r2, unsigned& r3, unsigned addr)
{
    asm volatile("ldmatrix.sync.aligned.m8n8.x4.shared.b16 {%0,%1,%2,%3}, [%4];"
                 : "=r"(r0), "=r"(r1), "=r"(r2), "=r"(r3) : "r"(addr));
}

__device__ __forceinline__ void ldsm4t(unsigned& r0, unsigned& r1,
                                       unsigned& r2, unsigned& r3, unsigned addr)
{
    asm volatile("ldmatrix.sync.aligned.m8n8.x4.trans.shared.b16 {%0,%1,%2,%3}, [%4];"
                 : "=r"(r0), "=r"(r1), "=r"(r2), "=r"(r3) : "r"(addr));
}

__device__ __forceinline__ void cpa16(unsigned dst, const void* src) {
    asm volatile("cp.async.cg.shared.global [%0], [%1], 16;" :: "r"(dst), "l"(src));
}
__device__ __forceinline__ void cpa_commit() { asm volatile("cp.async.commit_group;"); }
__device__ __forceinline__ void cpa_wait1()  { asm volatile("cp.async.wait_group 1;"); }
__device__ __forceinline__ void cpa_wait0()  { asm volatile("cp.async.wait_group 0;"); }

__device__ __forceinline__ unsigned h2u(float a, float b) {
    __half2 h = __floats2half2_rn(a, b);
    return *(unsigned*)&h;
}

__device__ __forceinline__ float ex2f(float x) {
    float y; asm("ex2.approx.f32 %0, %1;" : "=f"(y) : "f"(x)); return y;
}
__device__ __forceinline__ float lg2f(float x) {
    float y; asm("lg2.approx.f32 %0, %1;" : "=f"(y) : "f"(x)); return y;
}

// ---------------- kernel 1: hash + bucket + key norm + Q,V->fp16 ---------
#define SQ_STR 68
#define HASH_SMEM (128*SQ_STR*4 + 64*64*4)   // sQ[128][68] + sR[64][64]

__global__ void __launch_bounds__(128) hash_kernel(const float* __restrict__ query,
                                                   const float* __restrict__ value,
                                                   const float* __restrict__ randm)
{
    extern __shared__ float hs[];
    float* sQ = hs;                 // [128][68]
    float* sR = hs + 128*SQ_STR;    // [64][64]  d-major, rk = r*16+k
    const int b   = blockIdx.y;
    const int tid = threadIdx.x;

    for (int i = tid; i < 1024; i += 128)
        *(float4*)&sR[i*4] = *(const float4*)&randm[b*4096 + i*4];
    const size_t qbase = ((size_t)b*S + (size_t)blockIdx.x*128)*D;
    for (int i = tid; i < 2048; i += 128) {           // coalesced float4
        float4 v = *(const float4*)&query[qbase + (size_t)i*4];
        int row = i >> 4, d4 = (i & 15) << 2;
        *(float4*)&sQ[row*SQ_STR + d4] = v;
        uint2 h;                                      // emit fp16 Q copy
        h.x = h2u(v.x, v.y);
        h.y = h2u(v.z, v.w);
        *(uint2*)&g_qh[qbase + (size_t)i*4] = h;
    }
    for (int i = tid; i < 2048; i += 128) {           // fp16 V copy (fused)
        float4 v = *(const float4*)&value[qbase + (size_t)i*4];
        uint2 h;
        h.x = h2u(v.x, v.y);
        h.y = h2u(v.z, v.w);
        *(uint2*)&g_vh[qbase + (size_t)i*4] = h;
    }
    __syncthreads();

    const int t = blockIdx.x*128 + tid;
    const float* q = &sQ[tid*SQ_STR];

    float acc[64];
#pragma unroll
    for (int i = 0; i < 64; i++) acc[i] = 0.f;
    float nrm = 0.f;
    for (int d = 0; d < D; d++) {
        float qd = q[d];
        nrm += qd*qd;
        const float4* rr = (const float4*)&sR[d*64];
#pragma unroll
        for (int i4 = 0; i4 < 16; i4++) {
            float4 r4 = rr[i4];
            acc[i4*4+0] += qd * r4.x;
            acc[i4*4+1] += qd * r4.y;
            acc[i4*4+2] += qd * r4.z;
            acc[i4*4+3] += qd * r4.w;
        }
    }
    g_qninv[b*S + t] = rsqrtf(fmaxf(nrm, 1e-12f));

#pragma unroll
    for (int r = 0; r < R; r++) {
        float bv = acc[r*16];
        int   bi = 0;
#pragma unroll
        for (int k = 1; k < 16; k++) {
            float v = acc[r*16 + k];
            if (v > bv) { bv = v; bi = k; }
        }
#pragma unroll
        for (int k = 0; k < 16; k++) {
            float v = -acc[r*16 + k];
            if (v > bv) { bv = v; bi = 16 + k; }
        }
        g_bucket[(b*R + r)*S + t] = bi;
    }
}

// ---------------- kernel 2: stable counting sort per (b, r) --------------
__global__ void sort_kernel()
{
    __shared__ int hist[NB*256];   // bucket-major, thread-minor
    __shared__ int wtot[8];
    const int br  = blockIdx.x;
    const int tid = threadIdx.x;
    const int* bk = g_bucket  + br*S;
    int*     sidx = g_sortidx + br*S;

    for (int i = tid; i < NB*256; i += 256) hist[i] = 0;
    __syncthreads();

    const int base = tid*8;
    int myb[8];
#pragma unroll
    for (int k = 0; k < 8; k++) { myb[k] = bk[base + k]; hist[myb[k]*256 + tid]++; }
    __syncthreads();

    // exclusive scan over 8192 entries in index order (stable)
    int run = 0;
    for (int i = tid*32; i < tid*32 + 32; i++) { int v = hist[i]; hist[i] = run; run += v; }
    const int lane = tid & 31, wid = tid >> 5;
    int x = run;
#pragma unroll
    for (int off = 1; off < 32; off <<= 1) {
        int nv = __shfl_up_sync(0xffffffffu, x, off);
        if (lane >= off) x += nv;
    }
    if (lane == 31) wtot[wid] = x;
    __syncthreads();
    if (tid < 8) {
        int y = wtot[tid], z = y;
#pragma unroll
        for (int off = 1; off < 8; off <<= 1) {
            int nv = __shfl_up_sync(0x000000ffu, z, off);
            if (tid >= off) z += nv;
        }
        wtot[tid] = z - y;    // exclusive warp offsets
    }
    __syncthreads();
    const int add = (x - run) + wtot[wid];
    for (int i = tid*32; i < tid*32 + 32; i++) hist[i] += add;
    __syncthreads();

#pragma unroll
    for (int k = 0; k < 8; k++) {
        int bb  = myb[k];
        int rnk = hist[bb*256 + tid]++;
        sidx[rnk] = base + k;
    }
}

// ---------------- kernel 3: bucketed attention, 4 warps, full-n per warp -
// All-fp16 MMA; P lives in registers. Masks via explicit per-key position
// comparisons; {ki, sc} interleaved in smem so the mask loop fetches both
// columns' key+scale with ONE LDS.128 per n-tile. Softmax runs in log2
// domain (scale pre-multiplied by log2e; raw ex2/lg2).
// smem layout (bytes):
//   [0,4096)        ksc2  : int[1024]         {ki, sc_log2_bits} pairs x512
//   [4096,6144)     cinvS : float[512]        1/duplicate-count
//   [6144,28672)    ksh   : half[128][88]     Q/K window tile (rows 64.. = Q)
//   [28672,51200)   vsh   : half[128][88]     V tile (cnt int[2048] aliases
//                                              during phase 0, before V0 load)
#define KSH_STR 88
#define VSH_STR 88
#define OFF_KSC   0
#define OFF_CINV  4096
#define OFF_KS    6144
#define OFF_VS    28672
#define ATTN_SMEM 51200

__global__ void __launch_bounds__(128, 4) attn_kernel()
{
    extern __shared__ char smem[];
    int*    ksc2  = (int*)   (smem + OFF_KSC);
    float*  cinvS = (float*) (smem + OFF_CINV);
    int*    cnt   = (int*)   (smem + OFF_VS);   // alias (phase 0 only)

    const int blk = blockIdx.x;
    const int b   = blk >> 5;
    const int n   = blk & 31;
    const int tid = threadIdx.x;
    const int l   = tid & 31;
    const int mi  = tid >> 5;   // warp = m-tile (16 rows)

    const int* sidx_b = g_sortidx + b*R*S;
    const int  prev   = (n + 31) & 31;
    const float* qn   = g_qninv + b*S;
    const __half* Qh  = g_qh + (size_t)b*S*D;
    const __half* Vh  = g_vh + (size_t)b*S*D;

    const unsigned ks_s = (unsigned)__cvta_generic_to_shared(smem + OFF_KS);
    const unsigned vs_s = (unsigned)__cvta_generic_to_shared(smem + OFF_VS);
    const int i0 = mi*16 + (l>>2);

    // per-lane ldmatrix base addresses (bytes)
    const unsigned aG1 = ks_s + (unsigned)((64 + mi*16 + (l & 15))*KSH_STR)*2
                              + ((l >> 4) << 4);
    const unsigned bG1 = ks_s + (unsigned)(((l & 7) + ((l & 16) >> 1))*KSH_STR)*2
                              + (((l >> 3) & 1) << 4);
    const unsigned bG2 = vs_s + (unsigned)((l & 15)*VSH_STR)*2 + ((l >> 4) << 4);

    // ---- phase 0a: window key positions ----
    for (int idx = tid; idx < 512; idx += 128) {
        int r = idx >> 7, j = idx & 127;
        int slot = (j < 64) ? (prev*64 + j) : (n*64 + j - 64);
        ksc2[idx*2] = sidx_b[r*S + slot];
    }
    __syncthreads();

    // ---- prologue: K0 load starts now (overlaps counting) ----
    {
#pragma unroll
        for (int it = 0; it < 8; it++) {         // 1024 x 16B
            int idx = it*128 + tid, row = idx >> 3, c8 = (idx & 7) << 3;
            cpa16(ks_s + (unsigned)row*(KSH_STR*2) + c8*2,
                  &Qh[(size_t)ksc2[row*2]*D + c8]);
        }
        cpa_commit();
    }

    // ---- phase 0b: multiplicity counts + scales (cnt lives in vsh) ----
    for (int idx = tid; idx < 2048; idx += 128) cnt[idx] = 0;
    __syncthreads();
    for (int idx = tid; idx < 512; idx += 128) atomicAdd(&cnt[ksc2[idx*2]], 1);
    __syncthreads();
    for (int idx = tid; idx < 512; idx += 128) {
        int kp = ksc2[idx*2];
        cinvS[idx]    = 1.f / (float)cnt[kp];
        ksc2[idx*2+1] = __float_as_int(qn[kp] * (0.125f * LOG2E_F));
    }
    __syncthreads();   // all cnt reads done; vsh free for V0

    // ---- prologue: V0 load ----
    {
#pragma unroll
        for (int it = 0; it < 8; it++) {
            int idx = it*128 + tid, row = idx >> 3, c8 = (idx & 7) << 3;
            cpa16(vs_s + (unsigned)row*(VSH_STR*2) + c8*2,
                  &Vh[(size_t)ksc2[row*2]*D + c8]);
        }
        cpa_commit();
    }

    for (int r = 0; r < R; r++) {
        const int rb = r*128;

        // ---- K(r) ready (oldest outstanding group) ----
        cpa_wait1();
        __syncthreads();

        // ---- GEMM1 (fp16): S[16x128] per warp = Q(rows 64..127) . K^T ----
        float acc[16][4];
#pragma unroll
        for (int t2 = 0; t2 < 16; t2++)
#pragma unroll
            for (int c = 0; c < 4; c++) acc[t2][c] = 0.f;

        unsigned af[4][4];                           // A frags, 4 k16 chunks
#pragma unroll
        for (int c = 0; c < 4; c++)
            ldsm4(af[c][0], af[c][1], af[c][2], af[c][3], aG1 + c*32);

#pragma unroll
        for (int p = 0; p < 8; p++) {                // n-tile pairs 2p, 2p+1
#pragma unroll
            for (int c = 0; c < 4; c++) {            // k16 chunks
                unsigned b0,b1,b2,b3;
                ldsm4(b0,b1,b2,b3, bG1 + (unsigned)(p*16*KSH_STR)*2 + c*32);
                mma_f16(acc[2*p],   af[c], b0, b1);
                mma_f16(acc[2*p+1], af[c], b2, b3);
            }
        }
        __syncthreads();   // all warps' ksh reads done

        // ---- prefetch K(r+1) into ksh (overlaps softmax + GEMM2) ----
        if (r < R-1) {
#pragma unroll
            for (int it = 0; it < 8; it++) {
                int idx = it*128 + tid, row = idx >> 3, c8 = (idx & 7) << 3;
                cpa16(ks_s + (unsigned)row*(KSH_STR*2) + c8*2,
                      &Qh[(size_t)ksc2[((r+1)*128 + row)*2]*D + c8]);
            }
            cpa_commit();
        }

        // ---- masks + log2-domain softmax (single warp per row) ----
        const int qpos0 = ksc2[(rb + 64 + i0)*2];
        const int qpos1 = ksc2[(rb + 64 + i0 + 8)*2];
        float m0 = -3.4e38f, m1 = -3.4e38f;
#pragma unroll
        for (int nt = 0; nt < 16; nt++) {
            int4 kk = *(const int4*)&ksc2[(rb + nt*8 + 2*(l&3))*2];
            float sc0 = __int_as_float(kk.y);
            float sc1 = __int_as_float(kk.w);
            float x0 = acc[nt][0] * sc0;
            if      (qpos0 <  kk.x) x0 = -1.0e9f*LOG2E_F;
            else if (qpos0 == kk.x) x0 = -1.0e5f*LOG2E_F;
            float x1 = acc[nt][1] * sc1;
            if      (qpos0 <  kk.z) x1 = -1.0e9f*LOG2E_F;
            else if (qpos0 == kk.z) x1 = -1.0e5f*LOG2E_F;
            float y0 = acc[nt][2] * sc0;
            if      (qpos1 <  kk.x) y0 = -1.0e9f*LOG2E_F;
            else if (qpos1 == kk.x) y0 = -1.0e5f*LOG2E_F;
            float y1 = acc[nt][3] * sc1;
            if      (qpos1 <  kk.z) y1 = -1.0e9f*LOG2E_F;
            else if (qpos1 == kk.z) y1 = -1.0e5f*LOG2E_F;
            acc[nt][0] = x0; acc[nt][1] = x1;
            acc[nt][2] = y0; acc[nt][3] = y1;
            m0 = fmaxf(m0, fmaxf(x0, x1));
            m1 = fmaxf(m1, fmaxf(y0, y1));
        }
        m0 = fmaxf(m0, __shfl_xor_sync(0xffffffffu, m0, 1));
        m0 = fmaxf(m0, __shfl_xor_sync(0xffffffffu, m0, 2));
        m1 = fmaxf(m1, __shfl_xor_sync(0xffffffffu, m1, 1));
        m1 = fmaxf(m1, __shfl_xor_sync(0xffffffffu, m1, 2));
        float s0 = 0.f, s1 = 0.f;
#pragma unroll
        for (int nt = 0; nt < 16; nt++)
#pragma unroll
            for (int e = 0; e < 2; e++) {
                float ex = ex2f(acc[nt][e]   - m0); acc[nt][e]   = ex; s0 += ex;
                float ey = ex2f(acc[nt][2+e] - m1); acc[nt][2+e] = ey; s1 += ey;
            }
        s0 += __shfl_xor_sync(0xffffffffu, s0, 1);
        s0 += __shfl_xor_sync(0xffffffffu, s0, 2);
        s1 += __shfl_xor_sync(0xffffffffu, s1, 1);
        s1 += __shfl_xor_sync(0xffffffffu, s1, 2);
        const float f0 = 1.f / s0;
        const float f1 = 1.f / s1;

        // ---- pack P into fp16 A-fragments (8 k16 chunks; no smem) ----
        unsigned ra[8][4];
#pragma unroll
        for (int t = 0; t < 8; t++) {
            int col0 = 16*t + 2*(l&3);
            float2 ci = *(float2*)&cinvS[rb + col0];
            float2 cj = *(float2*)&cinvS[rb + col0 + 8];
            ra[t][0] = h2u(acc[2*t][0]*f0*ci.x,   acc[2*t][1]*f0*ci.y);
            ra[t][1] = h2u(acc[2*t][2]*f1*ci.x,   acc[2*t][3]*f1*ci.y);
            ra[t][2] = h2u(acc[2*t+1][0]*f0*cj.x, acc[2*t+1][1]*f0*cj.y);
            ra[t][3] = h2u(acc[2*t+1][2]*f1*cj.x, acc[2*t+1][3]*f1*cj.y);
        }
        if ((l & 3) == 0) {
            g_lse[((size_t)b*S + qpos0)*R + r] = (m0 + lg2f(s0)) * LN2_F;
            g_lse[((size_t)b*S + qpos1)*R + r] = (m1 + lg2f(s1)) * LN2_F;
        }

        // ---- V(r) ready ----
        if (r < R-1) cpa_wait1(); else cpa_wait0();
        __syncthreads();

        // ---- GEMM2 (fp16): full 128-key k per warp, all 64 dims ----
        float acc2[8][4];
#pragma unroll
        for (int t2 = 0; t2 < 8; t2++)
#pragma unroll
            for (int c = 0; c < 4; c++) acc2[t2][c] = 0.f;

#pragma unroll
        for (int t = 0; t < 8; t++) {              // k16 chunks over 128 keys
#pragma unroll
            for (int p = 0; p < 4; p++) {          // dim tiles 2p, 2p+1
                unsigned b0,b1,b2,b3;
                ldsm4t(b0,b1,b2,b3, bG2 + (unsigned)(t*16*VSH_STR)*2 + p*32);
                mma_f16(acc2[2*p],   ra[t], b0, b1);
                mma_f16(acc2[2*p+1], ra[t], b2, b3);
            }
        }

        __half* o0 = g_att + (((size_t)b*S + qpos0)*R + r)*D;
        __half* o1 = g_att + (((size_t)b*S + qpos1)*R + r)*D;
#pragma unroll
        for (int j = 0; j < 8; j++) {
            int c0 = j*8 + 2*(l&3);
            *(__half2*)&o0[c0] = __floats2half2_rn(acc2[j][0], acc2[j][1]);
            *(__half2*)&o1[c0] = __floats2half2_rn(acc2[j][2], acc2[j][3]);
        }
        __syncthreads();   // all vsh reads done

        // ---- prefetch V(r+1) into vsh (overlaps next round's GEMM1) ----
        if (r < R-1) {
#pragma unroll
            for (int it = 0; it < 8; it++) {
                int idx = it*128 + tid, row = idx >> 3, c8 = (idx & 7) << 3;
                cpa16(vs_s + (unsigned)row*(VSH_STR*2) + c8*2,
                      &Vh[(size_t)ksc2[((r+1)*128 + row)*2]*D + c8]);
            }
            cpa_commit();
        }
    }
}

// ---------------- kernel 4: round combine, 2 rows per thread -------------
__global__ void __launch_bounds__(256) combine_kernel(float* __restrict__ out)
{
    const int tid = threadIdx.x;
    const int l   = tid & 31;                       // half2 index (2 dims)
    const int w   = tid >> 5;
    const int r0  = blockIdx.x*16 + w;              // b*S + t
    const int r1  = r0 + 8;

    float4 la = *(const float4*)(g_lse + (size_t)r0*R);
    float4 lb = *(const float4*)(g_lse + (size_t)r1*R);
    const __half2* a = (const __half2*)g_att + (size_t)r0*R*(D/2);
    const __half2* c = (const __half2*)g_att + (size_t)r1*R*(D/2);
    __half2 av0 = a[0*(D/2)+l], av1 = a[1*(D/2)+l], av2 = a[2*(D/2)+l], av3 = a[3*(D/2)+l];
    __half2 cv0 = c[0*(D/2)+l], cv1 = c[1*(D/2)+l], cv2 = c[2*(D/2)+l], cv3 = c[3*(D/2)+l];

    {
        float m  = fmaxf(fmaxf(la.x, la.y), fmaxf(la.z, la.w));
        float w0 = __expf(la.x - m), w1 = __expf(la.y - m);
        float w2 = __expf(la.z - m), w3 = __expf(la.w - m);
        float inv = 1.f / (w0 + w1 + w2 + w3);
        float2 a0 = __half22float2(av0), a1 = __half22float2(av1);
        float2 a2 = __half22float2(av2), a3 = __half22float2(av3);
        float2 res;
        res.x = (a0.x*w0 + a1.x*w1 + a2.x*w2 + a3.x*w3) * inv;
        res.y = (a0.y*w0 + a1.y*w1 + a2.y*w2 + a3.y*w3) * inv;
        *(float2*)&out[(size_t)r0*D + l*2] = res;
    }
    {
        float m  = fmaxf(fmaxf(lb.x, lb.y), fmaxf(lb.z, lb.w));
        float w0 = __expf(lb.x - m), w1 = __expf(lb.y - m);
        float w2 = __expf(lb.z - m), w3 = __expf(lb.w - m);
        float inv = 1.f / (w0 + w1 + w2 + w3);
        float2 a0 = __half22float2(cv0), a1 = __half22float2(cv1);
        float2 a2 = __half22float2(cv2), a3 = __half22float2(cv3);
        float2 res;
        res.x = (a0.x*w0 + a1.x*w1 + a2.x*w2 + a3.x*w3) * inv;
        res.y = (a0.y*w0 + a1.y*w1 + a2.y*w2 + a3.y*w3) * inv;
        *(float2*)&out[(size_t)r1*D + l*2] = res;
    }
}

// ---------------- launch --------------------------------------------------
extern "C" void kernel_launch(void* const* d_in, const int* in_sizes, int n_in,
                              void* d_out, int out_size)
{
    const float* query = (const float*)d_in[0];
    const float* value = (const float*)d_in[1];
    const float* randm = (const float*)d_in[2];
    float* out = (float*)d_out;

    cudaFuncSetAttribute(hash_kernel,
                         cudaFuncAttributeMaxDynamicSharedMemorySize, HASH_SMEM);
    cudaFuncSetAttribute(attn_kernel,
                         cudaFuncAttributeMaxDynamicSharedMemorySize, ATTN_SMEM);

    hash_kernel<<<dim3(S/128, B), 128, HASH_SMEM>>>(query, value, randm);
    sort_kernel<<<B*R, 256>>>();
    attn_kernel<<<B*NB, 128, ATTN_SMEM>>>();
    combine_kernel<<<(B*S)/16, 256>>>(out);
}

// round 15
// speedup vs baseline: 1.1444x; 1.1444x over previous
#include <cuda_runtime.h>
#include <cuda_fp16.h>
#include <math.h>

#define B  32
#define S  2048
#define D  64
#define R  4
#define NB 32

// ---------------- scratch (device globals; no allocation) ----------------
__device__ int    g_bucket[B*R*S];            // 1 MB
__device__ int    g_sortidx[B*R*S];           // 1 MB
__device__ float  g_qninv[B*S];               // 256 KB
__device__ __half g_qh[(size_t)B*S*D];        // 8 MB   fp16 copy of query
__device__ __half g_vh[(size_t)B*S*D];        // 8 MB   fp16 copy of value
__device__ __half g_att[(size_t)B*S*R*D];     // 32 MB  [b][t][r][d]
__device__ float  g_lse[B*S*R];               // 1 MB   [b][t][r]

// ---------------- mma / cp.async / ldmatrix helpers ----------------------
__device__ __forceinline__ void mma_f16(float* c, const unsigned* a,
                                        unsigned b0, unsigned b1)
{
    asm volatile(
        "mma.sync.aligned.m16n8k16.row.col.f32.f16.f16.f32 "
        "{%0,%1,%2,%3}, {%4,%5,%6,%7}, {%8,%9}, {%0,%1,%2,%3};"
        : "+f"(c[0]), "+f"(c[1]), "+f"(c[2]), "+f"(c[3])
        : "r"(a[0]), "r"(a[1]), "r"(a[2]), "r"(a[3]), "r"(b0), "r"(b1));
}

__device__ __forceinline__ void ldsm4(unsigned& r0, unsigned& r1,
                                      unsigned& r2, unsigned& r3, unsigned addr)
{
    asm volatile("ldmatrix.sync.aligned.m8n8.x4.shared.b16 {%0,%1,%2,%3}, [%4];"
                 : "=r"(r0), "=r"(r1), "=r"(r2), "=r"(r3) : "r"(addr));
}

__device__ __forceinline__ void ldsm4t(unsigned& r0, unsigned& r1,
                                       unsigned& r2, unsigned& r3, unsigned addr)
{
    asm volatile("ldmatrix.sync.aligned.m8n8.x4.trans.shared.b16 {%0,%1,%2,%3}, [%4];"
                 : "=r"(r0), "=r"(r1), "=r"(r2), "=r"(r3) : "r"(addr));
}

__device__ __forceinline__ void cpa16(unsigned dst, const void* src) {
    asm volatile("cp.async.cg.shared.global [%0], [%1], 16;" :: "r"(dst), "l"(src));
}
__device__ __forceinline__ void cpa_commit() { asm volatile("cp.async.commit_group;"); }
__device__ __forceinline__ void cpa_wait1()  { asm volatile("cp.async.wait_group 1;"); }
__device__ __forceinline__ void cpa_wait0()  { asm volatile("cp.async.wait_group 0;"); }

__device__ __forceinline__ unsigned h2u(float a, float b) {
    __half2 h = __floats2half2_rn(a, b);
    return *(unsigned*)&h;
}

// ---------------- kernel 1: hash + bucket + key norm + Q,V->fp16 ---------
// Projection uses fma.rn.f32x2 (exact per-lane fp32; verified bit-identical)
// with DIRECT b64 smem loads so no repack movs are needed.
#define SQ_STR 65    // odd stride: scalar q reads conflict-free
#define HASH_SMEM (128*SQ_STR*4 + 64*64*4)   // sQ[128][65] + sR[64][64]

__global__ void __launch_bounds__(128) hash_kernel(const float* __restrict__ query,
                                                   const float* __restrict__ value,
                                                   const float* __restrict__ randm)
{
    extern __shared__ float hs[];
    float* sQ = hs;                 // [128][65]
    float* sR = hs + 128*SQ_STR;    // [64][64]  d-major, rk = r*16+k (16B aligned)
    const int b   = blockIdx.y;
    const int tid = threadIdx.x;

    for (int i = tid; i < 1024; i += 128)
        *(float4*)&sR[i*4] = *(const float4*)&randm[b*4096 + i*4];
    const size_t qbase = ((size_t)b*S + (size_t)blockIdx.x*128)*D;
    for (int i = tid; i < 2048; i += 128) {           // coalesced float4
        float4 v = *(const float4*)&query[qbase + (size_t)i*4];
        int row = i >> 4, d4 = (i & 15) << 2;
        float* p = &sQ[row*SQ_STR + d4];
        p[0] = v.x; p[1] = v.y; p[2] = v.z; p[3] = v.w;
        uint2 h;                                      // emit fp16 Q copy
        h.x = h2u(v.x, v.y);
        h.y = h2u(v.z, v.w);
        *(uint2*)&g_qh[qbase + (size_t)i*4] = h;
    }
    for (int i = tid; i < 2048; i += 128) {           // fp16 V copy (fused)
        float4 v = *(const float4*)&value[qbase + (size_t)i*4];
        uint2 h;
        h.x = h2u(v.x, v.y);
        h.y = h2u(v.z, v.w);
        *(uint2*)&g_vh[qbase + (size_t)i*4] = h;
    }
    __syncthreads();

    const int t = blockIdx.x*128 + tid;
    const float* q = &sQ[tid*SQ_STR];

    unsigned long long acc2[32];
#pragma unroll
    for (int i = 0; i < 32; i++) acc2[i] = 0ULL;      // packed (0.f, 0.f)
    float nrm = 0.f;
    for (int d = 0; d < D; d++) {
        float qd = q[d];                              // conflict-free LDS
        nrm += qd*qd;
        unsigned long long q2;
        asm("mov.b64 %0, {%1, %1};" : "=l"(q2) : "f"(qd));
        const ulonglong2* rr = (const ulonglong2*)&sR[d*64];
#pragma unroll
        for (int i = 0; i < 16; i++) {
            ulonglong2 r2 = rr[i];                    // LDS.128 -> 2 b64 pairs
            asm("fma.rn.f32x2 %0, %1, %2, %0;" : "+l"(acc2[2*i])   : "l"(q2), "l"(r2.x));
            asm("fma.rn.f32x2 %0, %1, %2, %0;" : "+l"(acc2[2*i+1]) : "l"(q2), "l"(r2.y));
        }
    }
    g_qninv[b*S + t] = rsqrtf(fmaxf(nrm, 1e-12f));

    float acc[64];
#pragma unroll
    for (int i = 0; i < 32; i++) {
        float lo, hi;
        asm("mov.b64 {%0, %1}, %2;" : "=f"(lo), "=f"(hi) : "l"(acc2[i]));
        acc[2*i] = lo; acc[2*i+1] = hi;
    }

#pragma unroll
    for (int r = 0; r < R; r++) {
        float bv = acc[r*16];
        int   bi = 0;
#pragma unroll
        for (int k = 1; k < 16; k++) {
            float v = acc[r*16 + k];
            if (v > bv) { bv = v; bi = k; }
        }
#pragma unroll
        for (int k = 0; k < 16; k++) {
            float v = -acc[r*16 + k];
            if (v > bv) { bv = v; bi = 16 + k; }
        }
        g_bucket[(b*R + r)*S + t] = bi;
    }
}

// ---------------- kernel 2: stable counting sort per (b, r) --------------
__global__ void sort_kernel()
{
    __shared__ int hist[NB*256];   // bucket-major, thread-minor
    __shared__ int wtot[8];
    const int br  = blockIdx.x;
    const int tid = threadIdx.x;
    const int* bk = g_bucket  + br*S;
    int*     sidx = g_sortidx + br*S;

    for (int i = tid; i < NB*256; i += 256) hist[i] = 0;
    __syncthreads();

    const int base = tid*8;
    int myb[8];
    {
        int4 b0 = *(const int4*)&bk[base];
        int4 b1 = *(const int4*)&bk[base + 4];
        myb[0]=b0.x; myb[1]=b0.y; myb[2]=b0.z; myb[3]=b0.w;
        myb[4]=b1.x; myb[5]=b1.y; myb[6]=b1.z; myb[7]=b1.w;
    }
#pragma unroll
    for (int k = 0; k < 8; k++) hist[myb[k]*256 + tid]++;
    __syncthreads();

    // exclusive scan over 8192 entries in index order (stable);
    // per-thread 32-entry chunk staged through registers (no LDS->STS chain)
    int vals[32];
#pragma unroll
    for (int j = 0; j < 32; j++) vals[j] = hist[tid*32 + j];
    int run = 0;
#pragma unroll
    for (int j = 0; j < 32; j++) { int v = vals[j]; vals[j] = run; run += v; }
    const int lane = tid & 31, wid = tid >> 5;
    int x = run;
#pragma unroll
    for (int off = 1; off < 32; off <<= 1) {
        int nv = __shfl_up_sync(0xffffffffu, x, off);
        if (lane >= off) x += nv;
    }
    if (lane == 31) wtot[wid] = x;
    __syncthreads();
    if (tid < 8) {
        int y = wtot[tid], z = y;
#pragma unroll
        for (int off = 1; off < 8; off <<= 1) {
            int nv = __shfl_up_sync(0x000000ffu, z, off);
            if (tid >= off) z += nv;
        }
        wtot[tid] = z - y;    // exclusive warp offsets
    }
    __syncthreads();
    const int add = (x - run) + wtot[wid];
#pragma unroll
    for (int j = 0; j < 32; j++) hist[tid*32 + j] = vals[j] + add;
    __syncthreads();

#pragma unroll
    for (int k = 0; k < 8; k++) {
        int bb  = myb[k];
        int rnk = hist[bb*256 + tid]++;
        sidx[rnk] = base + k;
    }
}

// ---------------- kernel 3: bucketed attention (R11 known-good form) -----
// All-fp16 MMA; P lives in registers. Explicit per-key position masks.
// smem layout (bytes):
//   [0,2048)        kiS   : int[512]          window key positions, per round
//   [2048,4096)     cinvS : float[512]        1/duplicate-count
//   [4096,6144)     scS   : float[512]        per-key qn*0.125 scale
//   [6144,28672)    ksh   : half[128][88]     Q/K window tile (rows 64.. = Q)
//   [28672,51200)   vsh   : half[128][88]     V tile (cnt int[2048] aliases
//                                              during phase 0, before V0 load)
#define KSH_STR 88
#define VSH_STR 88
#define OFF_KI    0
#define OFF_CINV  2048
#define OFF_SC    4096
#define OFF_KS    6144
#define OFF_VS    28672
#define ATTN_SMEM 51200

__global__ void __launch_bounds__(128, 4) attn_kernel()
{
    extern __shared__ char smem[];
    int*    kiS   = (int*)   (smem + OFF_KI);
    float*  cinvS = (float*) (smem + OFF_CINV);
    float*  scS   = (float*) (smem + OFF_SC);
    int*    cnt   = (int*)   (smem + OFF_VS);   // alias (phase 0 only)

    const int blk = blockIdx.x;
    const int b   = blk >> 5;
    const int n   = blk & 31;
    const int tid = threadIdx.x;
    const int l   = tid & 31;
    const int mi  = tid >> 5;   // warp = m-tile (16 rows)

    const int* sidx_b = g_sortidx + b*R*S;
    const int  prev   = (n + 31) & 31;
    const float* qn   = g_qninv + b*S;
    const __half* Qh  = g_qh + (size_t)b*S*D;
    const __half* Vh  = g_vh + (size_t)b*S*D;

    const unsigned ks_s = (unsigned)__cvta_generic_to_shared(smem + OFF_KS);
    const unsigned vs_s = (unsigned)__cvta_generic_to_shared(smem + OFF_VS);
    const int i0 = mi*16 + (l>>2);

    // per-lane ldmatrix base addresses (bytes)
    const unsigned aG1 = ks_s + (unsigned)((64 + mi*16 + (l & 15))*KSH_STR)*2
                              + ((l >> 4) << 4);
    const unsigned bG1 = ks_s + (unsigned)(((l & 7) + ((l & 16) >> 1))*KSH_STR)*2
                              + (((l >> 3) & 1) << 4);
    const unsigned bG2 = vs_s + (unsigned)((l & 15)*VSH_STR)*2 + ((l >> 4) << 4);

    // ---- phase 0a: window key positions ----
    for (int idx = tid; idx < 512; idx += 128) {
        int r = idx >> 7, j = idx & 127;
        int slot = (j < 64) ? (prev*64 + j) : (n*64 + j - 64);
        kiS[idx] = sidx_b[r*S + slot];
    }
    __syncthreads();

    // ---- prologue: K0 load starts now (overlaps counting) ----
    {
        const int* ki = kiS;
#pragma unroll
        for (int it = 0; it < 8; it++) {         // 1024 x 16B
            int idx = it*128 + tid, row = idx >> 3, c8 = (idx & 7) << 3;
            cpa16(ks_s + (unsigned)row*(KSH_STR*2) + c8*2, &Qh[(size_t)ki[row]*D + c8]);
        }
        cpa_commit();
    }

    // ---- phase 0b: multiplicity counts + scales (cnt lives in vsh) ----
    for (int idx = tid; idx < 2048; idx += 128) cnt[idx] = 0;
    __syncthreads();
    for (int idx = tid; idx < 512; idx += 128) atomicAdd(&cnt[kiS[idx]], 1);
    __syncthreads();
    for (int idx = tid; idx < 512; idx += 128) {
        int kp = kiS[idx];
        cinvS[idx] = 1.f / (float)cnt[kp];
        scS[idx]   = qn[kp] * 0.125f;
    }
    __syncthreads();   // all cnt reads done; vsh free for V0

    // ---- prologue: V0 load ----
    {
        const int* ki = kiS;
#pragma unroll
        for (int it = 0; it < 8; it++) {
            int idx = it*128 + tid, row = idx >> 3, c8 = (idx & 7) << 3;
            cpa16(vs_s + (unsigned)row*(VSH_STR*2) + c8*2, &Vh[(size_t)ki[row]*D + c8]);
        }
        cpa_commit();
    }

    for (int r = 0; r < R; r++) {
        const int* ki = kiS + r*128;

        // ---- K(r) ready (oldest outstanding group) ----
        cpa_wait1();
        __syncthreads();

        // ---- GEMM1 (fp16): S[16x128] per warp = Q(rows 64..127) . K^T ----
        float acc[16][4];
#pragma unroll
        for (int t2 = 0; t2 < 16; t2++)
#pragma unroll
            for (int c = 0; c < 4; c++) acc[t2][c] = 0.f;

        unsigned af[4][4];                           // A frags, 4 k16 chunks
#pragma unroll
        for (int c = 0; c < 4; c++)
            ldsm4(af[c][0], af[c][1], af[c][2], af[c][3], aG1 + c*32);

#pragma unroll
        for (int p = 0; p < 8; p++) {                // n-tile pairs 2p, 2p+1
#pragma unroll
            for (int c = 0; c < 4; c++) {            // k16 chunks
                unsigned b0,b1,b2,b3;
                ldsm4(b0,b1,b2,b3, bG1 + (unsigned)(p*16*KSH_STR)*2 + c*32);
                mma_f16(acc[2*p],   af[c], b0, b1);
                mma_f16(acc[2*p+1], af[c], b2, b3);
            }
        }
        __syncthreads();   // all warps' ksh reads done

        // ---- prefetch K(r+1) into ksh (overlaps softmax + GEMM2) ----
        if (r < R-1) {
            const int* kin = kiS + (r+1)*128;
#pragma unroll
            for (int it = 0; it < 8; it++) {
                int idx = it*128 + tid, row = idx >> 3, c8 = (idx & 7) << 3;
                cpa16(ks_s + (unsigned)row*(KSH_STR*2) + c8*2, &Qh[(size_t)kin[row]*D + c8]);
            }
            cpa_commit();
        }

        // ---- in-register scale + masks + softmax (single warp per row) --
        const int qpos0 = ki[64 + i0];
        const int qpos1 = ki[64 + i0 + 8];
        float m0 = -3.4e38f, m1 = -3.4e38f;
#pragma unroll
        for (int nt = 0; nt < 16; nt++) {
#pragma unroll
            for (int e = 0; e < 2; e++) {
                int col = nt*8 + 2*(l&3) + e;
                int kp  = ki[col];
                float sc = scS[r*128 + col];
                float x = acc[nt][e] * sc;
                if      (qpos0 <  kp) x = -1.0e9f;
                else if (qpos0 == kp) x = -1.0e5f;
                acc[nt][e] = x; m0 = fmaxf(m0, x);
                float y = acc[nt][2+e] * sc;
                if      (qpos1 <  kp) y = -1.0e9f;
                else if (qpos1 == kp) y = -1.0e5f;
                acc[nt][2+e] = y; m1 = fmaxf(m1, y);
            }
        }
        m0 = fmaxf(m0, __shfl_xor_sync(0xffffffffu, m0, 1));
        m0 = fmaxf(m0, __shfl_xor_sync(0xffffffffu, m0, 2));
        m1 = fmaxf(m1, __shfl_xor_sync(0xffffffffu, m1, 1));
        m1 = fmaxf(m1, __shfl_xor_sync(0xffffffffu, m1, 2));
        float s0 = 0.f, s1 = 0.f;
#pragma unroll
        for (int nt = 0; nt < 16; nt++)
#pragma unroll
            for (int e = 0; e < 2; e++) {
                float ex = __expf(acc[nt][e]   - m0); acc[nt][e]   = ex; s0 += ex;
                float ey = __expf(acc[nt][2+e] - m1); acc[nt][2+e] = ey; s1 += ey;
            }
        s0 += __shfl_xor_sync(0xffffffffu, s0, 1);
        s0 += __shfl_xor_sync(0xffffffffu, s0, 2);
        s1 += __shfl_xor_sync(0xffffffffu, s1, 1);
        s1 += __shfl_xor_sync(0xffffffffu, s1, 2);
        const float f0 = 1.f / s0;
        const float f1 = 1.f / s1;

        // ---- pack P into fp16 A-fragments (8 k16 chunks; no smem) ----
        unsigned ra[8][4];
#pragma unroll
        for (int t = 0; t < 8; t++) {
            int col0 = 16*t + 2*(l&3);
            float2 ci = *(float2*)&cinvS[r*128 + col0];
            float2 cj = *(float2*)&cinvS[r*128 + col0 + 8];
            ra[t][0] = h2u(acc[2*t][0]*f0*ci.x,   acc[2*t][1]*f0*ci.y);
            ra[t][1] = h2u(acc[2*t][2]*f1*ci.x,   acc[2*t][3]*f1*ci.y);
            ra[t][2] = h2u(acc[2*t+1][0]*f0*cj.x, acc[2*t+1][1]*f0*cj.y);
            ra[t][3] = h2u(acc[2*t+1][2]*f1*cj.x, acc[2*t+1][3]*f1*cj.y);
        }
        if ((l & 3) == 0) {
            g_lse[((size_t)b*S + qpos0)*R + r] = m0 + __logf(s0);
            g_lse[((size_t)b*S + qpos1)*R + r] = m1 + __logf(s1);
        }

        // ---- V(r) ready ----
        if (r < R-1) cpa_wait1(); else cpa_wait0();
        __syncthreads();

        // ---- GEMM2 (fp16): full 128-key k per warp, all 64 dims ----
        float acc2[8][4];
#pragma unroll
        for (int t2 = 0; t2 < 8; t2++)
#pragma unroll
            for (int c = 0; c < 4; c++) acc2[t2][c] = 0.f;

#pragma unroll
        for (int t = 0; t < 8; t++) {              // k16 chunks over 128 keys
#pragma unroll
            for (int p = 0; p < 4; p++) {          // dim tiles 2p, 2p+1
                unsigned b0,b1,b2,b3;
                ldsm4t(b0,b1,b2,b3, bG2 + (unsigned)(t*16*VSH_STR)*2 + p*32);
                mma_f16(acc2[2*p],   ra[t], b0, b1);
                mma_f16(acc2[2*p+1], ra[t], b2, b3);
            }
        }

        __half* o0 = g_att + (((size_t)b*S + qpos0)*R + r)*D;
        __half* o1 = g_att + (((size_t)b*S + qpos1)*R + r)*D;
#pragma unroll
        for (int j = 0; j < 8; j++) {
            int c0 = j*8 + 2*(l&3);
            *(__half2*)&o0[c0] = __floats2half2_rn(acc2[j][0], acc2[j][1]);
            *(__half2*)&o1[c0] = __floats2half2_rn(acc2[j][2], acc2[j][3]);
        }
        __syncthreads();   // all vsh reads done

        // ---- prefetch V(r+1) into vsh (overlaps next round's GEMM1) ----
        if (r < R-1) {
            const int* kin = kiS + (r+1)*128;
#pragma unroll
            for (int it = 0; it < 8; it++) {
                int idx = it*128 + tid, row = idx >> 3, c8 = (idx & 7) << 3;
                cpa16(vs_s + (unsigned)row*(VSH_STR*2) + c8*2, &Vh[(size_t)kin[row]*D + c8]);
            }
            cpa_commit();
        }
    }
}

// ---------------- kernel 4: round combine, 2 rows per thread -------------
__global__ void __launch_bounds__(256) combine_kernel(float* __restrict__ out)
{
    const int tid = threadIdx.x;
    const int l   = tid & 31;                       // half2 index (2 dims)
    const int w   = tid >> 5;
    const int r0  = blockIdx.x*16 + w;              // b*S + t
    const int r1  = r0 + 8;

    float4 la = *(const float4*)(g_lse + (size_t)r0*R);
    float4 lb = *(const float4*)(g_lse + (size_t)r1*R);
    const __half2* a = (const __half2*)g_att + (size_t)r0*R*(D/2);
    const __half2* c = (const __half2*)g_att + (size_t)r1*R*(D/2);
    __half2 av0 = a[0*(D/2)+l], av1 = a[1*(D/2)+l], av2 = a[2*(D/2)+l], av3 = a[3*(D/2)+l];
    __half2 cv0 = c[0*(D/2)+l], cv1 = c[1*(D/2)+l], cv2 = c[2*(D/2)+l], cv3 = c[3*(D/2)+l];

    {
        float m  = fmaxf(fmaxf(la.x, la.y), fmaxf(la.z, la.w));
        float w0 = __expf(la.x - m), w1 = __expf(la.y - m);
        float w2 = __expf(la.z - m), w3 = __expf(la.w - m);
        float inv = 1.f / (w0 + w1 + w2 + w3);
        float2 a0 = __half22float2(av0), a1 = __half22float2(av1);
        float2 a2 = __half22float2(av2), a3 = __half22float2(av3);
        float2 res;
        res.x = (a0.x*w0 + a1.x*w1 + a2.x*w2 + a3.x*w3) * inv;
        res.y = (a0.y*w0 + a1.y*w1 + a2.y*w2 + a3.y*w3) * inv;
        *(float2*)&out[(size_t)r0*D + l*2] = res;
    }
    {
        float m  = fmaxf(fmaxf(lb.x, lb.y), fmaxf(lb.z, lb.w));
        float w0 = __expf(lb.x - m), w1 = __expf(lb.y - m);
        float w2 = __expf(lb.z - m), w3 = __expf(lb.w - m);
        float inv = 1.f / (w0 + w1 + w2 + w3);
        float2 a0 = __half22float2(cv0), a1 = __half22float2(cv1);
        float2 a2 = __half22float2(cv2), a3 = __half22float2(cv3);
        float2 res;
        res.x = (a0.x*w0 + a1.x*w1 + a2.x*w2 + a3.x*w3) * inv;
        res.y = (a0.y*w0 + a1.y*w1 + a2.y*w2 + a3.y*w3) * inv;
        *(float2*)&out[(size_t)r1*D + l*2] = res;
    }
}

// ---------------- launch --------------------------------------------------
extern "C" void kernel_launch(void* const* d_in, const int* in_sizes, int n_in,
                              void* d_out, int out_size)
{
    const float* query = (const float*)d_in[0];
    const float* value = (const float*)d_in[1];
    const float* randm = (const float*)d_in[2];
    float* out = (float*)d_out;

    cudaFuncSetAttribute(hash_kernel,
                         cudaFuncAttributeMaxDynamicSharedMemorySize, HASH_SMEM);
    cudaFuncSetAttribute(attn_kernel,
                         cudaFuncAttributeMaxDynamicSharedMemorySize, ATTN_SMEM);

    hash_kernel<<<dim3(S/128, B), 128, HASH_SMEM>>>(query, value, randm);
    sort_kernel<<<B*R, 256>>>();
    attn_kernel<<<B*NB, 128, ATTN_SMEM>>>();
    combine_kernel<<<(B*S)/16, 256>>>(out);
}

// round 16
// speedup vs baseline: 1.1491x; 1.0041x over previous
#include <cuda_runtime.h>
#include <cuda_fp16.h>
#include <math.h>

#define B  32
#define S  2048
#define D  64
#define R  4
#define NB 32

// ---------------- scratch (device globals; no allocation) ----------------
__device__ int    g_bucket[B*R*S];            // 1 MB
__device__ int    g_sortidx[B*R*S];           // 1 MB
__device__ float  g_qninv[B*S];               // 256 KB
__device__ __half g_qh[(size_t)B*S*D];        // 8 MB   fp16 copy of query
__device__ __half g_vh[(size_t)B*S*D];        // 8 MB   fp16 copy of value
__device__ __half g_att[(size_t)B*S*R*D];     // 32 MB  [b][t][r][d]
__device__ float  g_lse[B*S*R];               // 1 MB   [b][t][r]

// ---------------- mma / cp.async / ldmatrix helpers ----------------------
__device__ __forceinline__ void mma_f16(float* c, const unsigned* a,
                                        unsigned b0, unsigned b1)
{
    asm volatile(
        "mma.sync.aligned.m16n8k16.row.col.f32.f16.f16.f32 "
        "{%0,%1,%2,%3}, {%4,%5,%6,%7}, {%8,%9}, {%0,%1,%2,%3};"
        : "+f"(c[0]), "+f"(c[1]), "+f"(c[2]), "+f"(c[3])
        : "r"(a[0]), "r"(a[1]), "r"(a[2]), "r"(a[3]), "r"(b0), "r"(b1));
}

__device__ __forceinline__ void ldsm4(unsigned& r0, unsigned& r1,
                                      unsigned& r2, unsigned& r3, unsigned addr)
{
    asm volatile("ldmatrix.sync.aligned.m8n8.x4.shared.b16 {%0,%1,%2,%3}, [%4];"
                 : "=r"(r0), "=r"(r1), "=r"(r2), "=r"(r3) : "r"(addr));
}

__device__ __forceinline__ void ldsm4t(unsigned& r0, unsigned& r1,
                                       unsigned& r2, unsigned& r3, unsigned addr)
{
    asm volatile("ldmatrix.sync.aligned.m8n8.x4.trans.shared.b16 {%0,%1,%2,%3}, [%4];"
                 : "=r"(r0), "=r"(r1), "=r"(r2), "=r"(r3) : "r"(addr));
}

__device__ __forceinline__ void cpa16(unsigned dst, const void* src) {
    asm volatile("cp.async.cg.shared.global [%0], [%1], 16;" :: "r"(dst), "l"(src));
}
__device__ __forceinline__ void cpa_commit() { asm volatile("cp.async.commit_group;"); }
__device__ __forceinline__ void cpa_wait1()  { asm volatile("cp.async.wait_group 1;"); }
__device__ __forceinline__ void cpa_wait0()  { asm volatile("cp.async.wait_group 0;"); }

__device__ __forceinline__ unsigned h2u(float a, float b) {
    __half2 h = __floats2half2_rn(a, b);
    return *(unsigned*)&h;
}

// ---------------- kernel 1: hash + bucket + key norm + Q,V->fp16 ---------
// Projection uses fma.rn.f32x2 (exact per-lane fp32; verified bit-identical)
// with DIRECT b64 smem loads so no repack movs are needed.
#define SQ_STR 65    // odd stride: scalar q reads conflict-free
#define HASH_SMEM (128*SQ_STR*4 + 64*64*4)   // sQ[128][65] + sR[64][64]

__global__ void __launch_bounds__(128) hash_kernel(const float* __restrict__ query,
                                                   const float* __restrict__ value,
                                                   const float* __restrict__ randm)
{
    extern __shared__ float hs[];
    float* sQ = hs;                 // [128][65]
    float* sR = hs + 128*SQ_STR;    // [64][64]  d-major, rk = r*16+k (16B aligned)
    const int b   = blockIdx.y;
    const int tid = threadIdx.x;

    for (int i = tid; i < 1024; i += 128)
        *(float4*)&sR[i*4] = *(const float4*)&randm[b*4096 + i*4];
    const size_t qbase = ((size_t)b*S + (size_t)blockIdx.x*128)*D;
    for (int i = tid; i < 2048; i += 128) {           // coalesced float4
        float4 v = *(const float4*)&query[qbase + (size_t)i*4];
        int row = i >> 4, d4 = (i & 15) << 2;
        float* p = &sQ[row*SQ_STR + d4];
        p[0] = v.x; p[1] = v.y; p[2] = v.z; p[3] = v.w;
        uint2 h;                                      // emit fp16 Q copy
        h.x = h2u(v.x, v.y);
        h.y = h2u(v.z, v.w);
        *(uint2*)&g_qh[qbase + (size_t)i*4] = h;
    }
    for (int i = tid; i < 2048; i += 128) {           // fp16 V copy (fused)
        float4 v = *(const float4*)&value[qbase + (size_t)i*4];
        uint2 h;
        h.x = h2u(v.x, v.y);
        h.y = h2u(v.z, v.w);
        *(uint2*)&g_vh[qbase + (size_t)i*4] = h;
    }
    __syncthreads();

    const int t = blockIdx.x*128 + tid;
    const float* q = &sQ[tid*SQ_STR];

    unsigned long long acc2[32];
#pragma unroll
    for (int i = 0; i < 32; i++) acc2[i] = 0ULL;      // packed (0.f, 0.f)
    float nrm = 0.f;
    for (int d = 0; d < D; d++) {
        float qd = q[d];                              // conflict-free LDS
        nrm += qd*qd;
        unsigned long long q2;
        asm("mov.b64 %0, {%1, %1};" : "=l"(q2) : "f"(qd));
        const ulonglong2* rr = (const ulonglong2*)&sR[d*64];
#pragma unroll
        for (int i = 0; i < 16; i++) {
            ulonglong2 r2 = rr[i];                    // LDS.128 -> 2 b64 pairs
            asm("fma.rn.f32x2 %0, %1, %2, %0;" : "+l"(acc2[2*i])   : "l"(q2), "l"(r2.x));
            asm("fma.rn.f32x2 %0, %1, %2, %0;" : "+l"(acc2[2*i+1]) : "l"(q2), "l"(r2.y));
        }
    }
    g_qninv[b*S + t] = rsqrtf(fmaxf(nrm, 1e-12f));

    float acc[64];
#pragma unroll
    for (int i = 0; i < 32; i++) {
        float lo, hi;
        asm("mov.b64 {%0, %1}, %2;" : "=f"(lo), "=f"(hi) : "l"(acc2[i]));
        acc[2*i] = lo; acc[2*i+1] = hi;
    }

#pragma unroll
    for (int r = 0; r < R; r++) {
        float bv = acc[r*16];
        int   bi = 0;
#pragma unroll
        for (int k = 1; k < 16; k++) {
            float v = acc[r*16 + k];
            if (v > bv) { bv = v; bi = k; }
        }
#pragma unroll
        for (int k = 0; k < 16; k++) {
            float v = -acc[r*16 + k];
            if (v > bv) { bv = v; bi = 16 + k; }
        }
        g_bucket[(b*R + r)*S + t] = bi;
    }
}

// ---------------- kernel 2: stable counting sort per (b, r) --------------
// Scatter staged through smem; global writes fully coalesced int4.
__global__ void sort_kernel()
{
    __shared__ int hist[NB*256];   // bucket-major, thread-minor (32 KB)
    __shared__ int sidx_s[S];      // staged output (8 KB)
    __shared__ int wtot[8];
    const int br  = blockIdx.x;
    const int tid = threadIdx.x;
    const int* bk = g_bucket  + br*S;
    int*     sidx = g_sortidx + br*S;

    for (int i = tid; i < NB*256; i += 256) hist[i] = 0;
    __syncthreads();

    const int base = tid*8;
    int myb[8];
    {
        int4 b0 = *(const int4*)&bk[base];
        int4 b1 = *(const int4*)&bk[base + 4];
        myb[0]=b0.x; myb[1]=b0.y; myb[2]=b0.z; myb[3]=b0.w;
        myb[4]=b1.x; myb[5]=b1.y; myb[6]=b1.z; myb[7]=b1.w;
    }
#pragma unroll
    for (int k = 0; k < 8; k++) hist[myb[k]*256 + tid]++;
    __syncthreads();

    // exclusive scan over 8192 entries in index order (stable);
    // per-thread 32-entry chunk staged through registers
    int vals[32];
#pragma unroll
    for (int j = 0; j < 32; j++) vals[j] = hist[tid*32 + j];
    int run = 0;
#pragma unroll
    for (int j = 0; j < 32; j++) { int v = vals[j]; vals[j] = run; run += v; }
    const int lane = tid & 31, wid = tid >> 5;
    int x = run;
#pragma unroll
    for (int off = 1; off < 32; off <<= 1) {
        int nv = __shfl_up_sync(0xffffffffu, x, off);
        if (lane >= off) x += nv;
    }
    if (lane == 31) wtot[wid] = x;
    __syncthreads();
    if (tid < 8) {
        int y = wtot[tid], z = y;
#pragma unroll
        for (int off = 1; off < 8; off <<= 1) {
            int nv = __shfl_up_sync(0x000000ffu, z, off);
            if (tid >= off) z += nv;
        }
        wtot[tid] = z - y;    // exclusive warp offsets
    }
    __syncthreads();
    const int add = (x - run) + wtot[wid];
#pragma unroll
    for (int j = 0; j < 32; j++) hist[tid*32 + j] = vals[j] + add;
    __syncthreads();

#pragma unroll
    for (int k = 0; k < 8; k++) {
        int bb  = myb[k];
        int rnk = hist[bb*256 + tid]++;
        sidx_s[rnk] = base + k;         // scattered STS (cheap)
    }
    __syncthreads();
    for (int i = tid; i < S/4; i += 256)               // coalesced 16B stores
        *(int4*)&sidx[i*4] = *(const int4*)&sidx_s[i*4];
}

// ---------------- kernel 3: bucketed attention (R11/R15 known-good form) -
// All-fp16 MMA; P lives in registers. Explicit per-key position masks.
// smem layout (bytes):
//   [0,2048)        kiS   : int[512]          window key positions, per round
//   [2048,4096)     cinvS : float[512]        1/duplicate-count
//   [4096,6144)     scS   : float[512]        per-key qn*0.125 scale
//   [6144,28672)    ksh   : half[128][88]     Q/K window tile (rows 64.. = Q)
//   [28672,51200)   vsh   : half[128][88]     V tile (cnt int[2048] aliases
//                                              during phase 0, before V0 load)
#define KSH_STR 88
#define VSH_STR 88
#define OFF_KI    0
#define OFF_CINV  2048
#define OFF_SC    4096
#define OFF_KS    6144
#define OFF_VS    28672
#define ATTN_SMEM 51200

__global__ void __launch_bounds__(128, 4) attn_kernel()
{
    extern __shared__ char smem[];
    int*    kiS   = (int*)   (smem + OFF_KI);
    float*  cinvS = (float*) (smem + OFF_CINV);
    float*  scS   = (float*) (smem + OFF_SC);
    int*    cnt   = (int*)   (smem + OFF_VS);   // alias (phase 0 only)

    const int blk = blockIdx.x;
    const int b   = blk >> 5;
    const int n   = blk & 31;
    const int tid = threadIdx.x;
    const int l   = tid & 31;
    const int mi  = tid >> 5;   // warp = m-tile (16 rows)

    const int* sidx_b = g_sortidx + b*R*S;
    const int  prev   = (n + 31) & 31;
    const float* qn   = g_qninv + b*S;
    const __half* Qh  = g_qh + (size_t)b*S*D;
    const __half* Vh  = g_vh + (size_t)b*S*D;

    const unsigned ks_s = (unsigned)__cvta_generic_to_shared(smem + OFF_KS);
    const unsigned vs_s = (unsigned)__cvta_generic_to_shared(smem + OFF_VS);
    const int i0 = mi*16 + (l>>2);

    // per-lane ldmatrix base addresses (bytes)
    const unsigned aG1 = ks_s + (unsigned)((64 + mi*16 + (l & 15))*KSH_STR)*2
                              + ((l >> 4) << 4);
    const unsigned bG1 = ks_s + (unsigned)(((l & 7) + ((l & 16) >> 1))*KSH_STR)*2
                              + (((l >> 3) & 1) << 4);
    const unsigned bG2 = vs_s + (unsigned)((l & 15)*VSH_STR)*2 + ((l >> 4) << 4);

    // ---- phase 0a: window key positions ----
    for (int idx = tid; idx < 512; idx += 128) {
        int r = idx >> 7, j = idx & 127;
        int slot = (j < 64) ? (prev*64 + j) : (n*64 + j - 64);
        kiS[idx] = sidx_b[r*S + slot];
    }
    __syncthreads();

    // ---- prologue: K0 load starts now (overlaps counting) ----
    {
        const int* ki = kiS;
#pragma unroll
        for (int it = 0; it < 8; it++) {         // 1024 x 16B
            int idx = it*128 + tid, row = idx >> 3, c8 = (idx & 7) << 3;
            cpa16(ks_s + (unsigned)row*(KSH_STR*2) + c8*2, &Qh[(size_t)ki[row]*D + c8]);
        }
        cpa_commit();
    }

    // ---- phase 0b: multiplicity counts + scales (cnt lives in vsh) ----
    for (int idx = tid; idx < 2048; idx += 128) cnt[idx] = 0;
    __syncthreads();
    for (int idx = tid; idx < 512; idx += 128) atomicAdd(&cnt[kiS[idx]], 1);
    __syncthreads();
    for (int idx = tid; idx < 512; idx += 128) {
        int kp = kiS[idx];
        cinvS[idx] = 1.f / (float)cnt[kp];
        scS[idx]   = qn[kp] * 0.125f;
    }
    __syncthreads();   // all cnt reads done; vsh free for V0

    // ---- prologue: V0 load ----
    {
        const int* ki = kiS;
#pragma unroll
        for (int it = 0; it < 8; it++) {
            int idx = it*128 + tid, row = idx >> 3, c8 = (idx & 7) << 3;
            cpa16(vs_s + (unsigned)row*(VSH_STR*2) + c8*2, &Vh[(size_t)ki[row]*D + c8]);
        }
        cpa_commit();
    }

    for (int r = 0; r < R; r++) {
        const int* ki = kiS + r*128;

        // ---- K(r) ready (oldest outstanding group) ----
        cpa_wait1();
        __syncthreads();

        // ---- GEMM1 (fp16): S[16x128] per warp = Q(rows 64..127) . K^T ----
        float acc[16][4];
#pragma unroll
        for (int t2 = 0; t2 < 16; t2++)
#pragma unroll
            for (int c = 0; c < 4; c++) acc[t2][c] = 0.f;

        unsigned af[4][4];                           // A frags, 4 k16 chunks
#pragma unroll
        for (int c = 0; c < 4; c++)
            ldsm4(af[c][0], af[c][1], af[c][2], af[c][3], aG1 + c*32);

#pragma unroll
        for (int p = 0; p < 8; p++) {                // n-tile pairs 2p, 2p+1
#pragma unroll
            for (int c = 0; c < 4; c++) {            // k16 chunks
                unsigned b0,b1,b2,b3;
                ldsm4(b0,b1,b2,b3, bG1 + (unsigned)(p*16*KSH_STR)*2 + c*32);
                mma_f16(acc[2*p],   af[c], b0, b1);
                mma_f16(acc[2*p+1], af[c], b2, b3);
            }
        }
        __syncthreads();   // all warps' ksh reads done

        // ---- prefetch K(r+1) into ksh (overlaps softmax + GEMM2) ----
        if (r < R-1) {
            const int* kin = kiS + (r+1)*128;
#pragma unroll
            for (int it = 0; it < 8; it++) {
                int idx = it*128 + tid, row = idx >> 3, c8 = (idx & 7) << 3;
                cpa16(ks_s + (unsigned)row*(KSH_STR*2) + c8*2, &Qh[(size_t)kin[row]*D + c8]);
            }
            cpa_commit();
        }

        // ---- in-register scale + masks + softmax (single warp per row) --
        const int qpos0 = ki[64 + i0];
        const int qpos1 = ki[64 + i0 + 8];
        float m0 = -3.4e38f, m1 = -3.4e38f;
#pragma unroll
        for (int nt = 0; nt < 16; nt++) {
#pragma unroll
            for (int e = 0; e < 2; e++) {
                int col = nt*8 + 2*(l&3) + e;
                int kp  = ki[col];
                float sc = scS[r*128 + col];
                float x = acc[nt][e] * sc;
                if      (qpos0 <  kp) x = -1.0e9f;
                else if (qpos0 == kp) x = -1.0e5f;
                acc[nt][e] = x; m0 = fmaxf(m0, x);
                float y = acc[nt][2+e] * sc;
                if      (qpos1 <  kp) y = -1.0e9f;
                else if (qpos1 == kp) y = -1.0e5f;
                acc[nt][2+e] = y; m1 = fmaxf(m1, y);
            }
        }
        m0 = fmaxf(m0, __shfl_xor_sync(0xffffffffu, m0, 1));
        m0 = fmaxf(m0, __shfl_xor_sync(0xffffffffu, m0, 2));
        m1 = fmaxf(m1, __shfl_xor_sync(0xffffffffu, m1, 1));
        m1 = fmaxf(m1, __shfl_xor_sync(0xffffffffu, m1, 2));
        float s0 = 0.f, s1 = 0.f;
#pragma unroll
        for (int nt = 0; nt < 16; nt++)
#pragma unroll
            for (int e = 0; e < 2; e++) {
                float ex = __expf(acc[nt][e]   - m0); acc[nt][e]   = ex; s0 += ex;
                float ey = __expf(acc[nt][2+e] - m1); acc[nt][2+e] = ey; s1 += ey;
            }
        s0 += __shfl_xor_sync(0xffffffffu, s0, 1);
        s0 += __shfl_xor_sync(0xffffffffu, s0, 2);
        s1 += __shfl_xor_sync(0xffffffffu, s1, 1);
        s1 += __shfl_xor_sync(0xffffffffu, s1, 2);
        const float f0 = 1.f / s0;
        const float f1 = 1.f / s1;

        // ---- pack P into fp16 A-fragments (8 k16 chunks; no smem) ----
        unsigned ra[8][4];
#pragma unroll
        for (int t = 0; t < 8; t++) {
            int col0 = 16*t + 2*(l&3);
            float2 ci = *(float2*)&cinvS[r*128 + col0];
            float2 cj = *(float2*)&cinvS[r*128 + col0 + 8];
            ra[t][0] = h2u(acc[2*t][0]*f0*ci.x,   acc[2*t][1]*f0*ci.y);
            ra[t][1] = h2u(acc[2*t][2]*f1*ci.x,   acc[2*t][3]*f1*ci.y);
            ra[t][2] = h2u(acc[2*t+1][0]*f0*cj.x, acc[2*t+1][1]*f0*cj.y);
            ra[t][3] = h2u(acc[2*t+1][2]*f1*cj.x, acc[2*t+1][3]*f1*cj.y);
        }
        if ((l & 3) == 0) {
            g_lse[((size_t)b*S + qpos0)*R + r] = m0 + __logf(s0);
            g_lse[((size_t)b*S + qpos1)*R + r] = m1 + __logf(s1);
        }

        // ---- V(r) ready ----
        if (r < R-1) cpa_wait1(); else cpa_wait0();
        __syncthreads();

        // ---- GEMM2 (fp16): full 128-key k per warp, all 64 dims ----
        float acc2[8][4];
#pragma unroll
        for (int t2 = 0; t2 < 8; t2++)
#pragma unroll
            for (int c = 0; c < 4; c++) acc2[t2][c] = 0.f;

#pragma unroll
        for (int t = 0; t < 8; t++) {              // k16 chunks over 128 keys
#pragma unroll
            for (int p = 0; p < 4; p++) {          // dim tiles 2p, 2p+1
                unsigned b0,b1,b2,b3;
                ldsm4t(b0,b1,b2,b3, bG2 + (unsigned)(t*16*VSH_STR)*2 + p*32);
                mma_f16(acc2[2*p],   ra[t], b0, b1);
                mma_f16(acc2[2*p+1], ra[t], b2, b3);
            }
        }

        __half* o0 = g_att + (((size_t)b*S + qpos0)*R + r)*D;
        __half* o1 = g_att + (((size_t)b*S + qpos1)*R + r)*D;
#pragma unroll
        for (int j = 0; j < 8; j++) {
            int c0 = j*8 + 2*(l&3);
            *(__half2*)&o0[c0] = __floats2half2_rn(acc2[j][0], acc2[j][1]);
            *(__half2*)&o1[c0] = __floats2half2_rn(acc2[j][2], acc2[j][3]);
        }
        __syncthreads();   // all vsh reads done

        // ---- prefetch V(r+1) into vsh (overlaps next round's GEMM1) ----
        if (r < R-1) {
            const int* kin = kiS + (r+1)*128;
#pragma unroll
            for (int it = 0; it < 8; it++) {
                int idx = it*128 + tid, row = idx >> 3, c8 = (idx & 7) << 3;
                cpa16(vs_s + (unsigned)row*(VSH_STR*2) + c8*2, &Vh[(size_t)kin[row]*D + c8]);
            }
            cpa_commit();
        }
    }
}

// ---------------- kernel 4: round combine, 8 threads per row, 16B ops ----
__global__ void __launch_bounds__(256) combine_kernel(float* __restrict__ out)
{
    const int tid = threadIdx.x;
    const int j   = tid & 7;                        // dim octet within row
    const int row = blockIdx.x*32 + (tid >> 3);     // b*S + t

    float4 lv = *(const float4*)(g_lse + (size_t)row*R);
    float m  = fmaxf(fmaxf(lv.x, lv.y), fmaxf(lv.z, lv.w));
    float w0 = __expf(lv.x - m), w1 = __expf(lv.y - m);
    float w2 = __expf(lv.z - m), w3 = __expf(lv.w - m);
    float inv = 1.f / (w0 + w1 + w2 + w3);

    const __half* abase = g_att + ((size_t)row*R)*D + j*8;
    uint4 q0 = *(const uint4*)(abase);              // round 0, 8 halves
    uint4 q1 = *(const uint4*)(abase + D);
    uint4 q2 = *(const uint4*)(abase + 2*D);
    uint4 q3 = *(const uint4*)(abase + 3*D);

    const __half2* h0 = (const __half2*)&q0;
    const __half2* h1 = (const __half2*)&q1;
    const __half2* h2 = (const __half2*)&q2;
    const __half2* h3 = (const __half2*)&q3;

    float res[8];
#pragma unroll
    for (int k = 0; k < 4; k++) {
        float2 a0 = __half22float2(h0[k]);
        float2 a1 = __half22float2(h1[k]);
        float2 a2 = __half22float2(h2[k]);
        float2 a3 = __half22float2(h3[k]);
        res[2*k]   = (a0.x*w0 + a1.x*w1 + a2.x*w2 + a3.x*w3) * inv;
        res[2*k+1] = (a0.y*w0 + a1.y*w1 + a2.y*w2 + a3.y*w3) * inv;
    }
    float* o = &out[(size_t)row*D + j*8];
    *(float4*)o       = make_float4(res[0], res[1], res[2], res[3]);
    *(float4*)(o + 4) = make_float4(res[4], res[5], res[6], res[7]);
}

// ---------------- launch --------------------------------------------------
extern "C" void kernel_launch(void* const* d_in, const int* in_sizes, int n_in,
                              void* d_out, int out_size)
{
    const float* query = (const float*)d_in[0];
    const float* value = (const float*)d_in[1];
    const float* randm = (const float*)d_in[2];
    float* out = (float*)d_out;

    cudaFuncSetAttribute(hash_kernel,
                         cudaFuncAttributeMaxDynamicSharedMemorySize, HASH_SMEM);
    cudaFuncSetAttribute(attn_kernel,
                         cudaFuncAttributeMaxDynamicSharedMemorySize, ATTN_SMEM);

    hash_kernel<<<dim3(S/128, B), 128, HASH_SMEM>>>(query, value, randm);
    sort_kernel<<<B*R, 256>>>();
    attn_kernel<<<B*NB, 128, ATTN_SMEM>>>();
    combine_kernel<<<(B*S)/32, 256>>>(out);
}

// round 17
// speedup vs baseline: 1.1514x; 1.0021x over previous
#include <cuda_runtime.h>
#include <cuda_fp16.h>
#include <math.h>

#define B  32
#define S  2048
#define D  64
#define R  4
#define NB 32

// ---------------- scratch (device globals; no allocation) ----------------
__device__ int    g_bucket[B*R*S];            // 1 MB
__device__ int    g_sortidx[B*R*S];           // 1 MB
__device__ float  g_qninv[B*S];               // 256 KB
__device__ __half g_qh[(size_t)B*S*D];        // 8 MB   fp16 copy of query
__device__ __half g_vh[(size_t)B*S*D];        // 8 MB   fp16 copy of value
__device__ __half g_att[(size_t)B*S*R*D];     // 32 MB  [b][t][r][d]
__device__ float  g_lse[B*S*R];               // 1 MB   [b][t][r]

// ---------------- mma / cp.async / ldmatrix helpers ----------------------
__device__ __forceinline__ void mma_f16(float* c, const unsigned* a,
                                        unsigned b0, unsigned b1)
{
    asm volatile(
        "mma.sync.aligned.m16n8k16.row.col.f32.f16.f16.f32 "
        "{%0,%1,%2,%3}, {%4,%5,%6,%7}, {%8,%9}, {%0,%1,%2,%3};"
        : "+f"(c[0]), "+f"(c[1]), "+f"(c[2]), "+f"(c[3])
        : "r"(a[0]), "r"(a[1]), "r"(a[2]), "r"(a[3]), "r"(b0), "r"(b1));
}

__device__ __forceinline__ void ldsm4(unsigned& r0, unsigned& r1,
                                      unsigned& r2, unsigned& r3, unsigned addr)
{
    asm volatile("ldmatrix.sync.aligned.m8n8.x4.shared.b16 {%0,%1,%2,%3}, [%4];"
                 : "=r"(r0), "=r"(r1), "=r"(r2), "=r"(r3) : "r"(addr));
}

__device__ __forceinline__ void ldsm4t(unsigned& r0, unsigned& r1,
                                       unsigned& r2, unsigned& r3, unsigned addr)
{
    asm volatile("ldmatrix.sync.aligned.m8n8.x4.trans.shared.b16 {%0,%1,%2,%3}, [%4];"
                 : "=r"(r0), "=r"(r1), "=r"(r2), "=r"(r3) : "r"(addr));
}

__device__ __forceinline__ void cpa16(unsigned dst, const void* src) {
    asm volatile("cp.async.cg.shared.global [%0], [%1], 16;" :: "r"(dst), "l"(src));
}
__device__ __forceinline__ void cpa_commit() { asm volatile("cp.async.commit_group;"); }
__device__ __forceinline__ void cpa_wait1()  { asm volatile("cp.async.wait_group 1;"); }
__device__ __forceinline__ void cpa_wait0()  { asm volatile("cp.async.wait_group 0;"); }

__device__ __forceinline__ unsigned h2u(float a, float b) {
    __half2 h = __floats2half2_rn(a, b);
    return *(unsigned*)&h;
}

// ---------------- kernel 1: hash + bucket + key norm + Q,V->fp16 ---------
// Projection uses fma.rn.f32x2 (exact per-lane fp32; verified bit-identical)
// with DIRECT b64 smem loads so no repack movs are needed.
#define SQ_STR 65    // odd stride: scalar q reads conflict-free
#define HASH_SMEM (128*SQ_STR*4 + 64*64*4)   // sQ[128][65] + sR[64][64]

__global__ void __launch_bounds__(128) hash_kernel(const float* __restrict__ query,
                                                   const float* __restrict__ value,
                                                   const float* __restrict__ randm)
{
    extern __shared__ float hs[];
    float* sQ = hs;                 // [128][65]
    float* sR = hs + 128*SQ_STR;    // [64][64]  d-major, rk = r*16+k (16B aligned)
    const int b   = blockIdx.y;
    const int tid = threadIdx.x;

    for (int i = tid; i < 1024; i += 128)
        *(float4*)&sR[i*4] = *(const float4*)&randm[b*4096 + i*4];
    const size_t qbase = ((size_t)b*S + (size_t)blockIdx.x*128)*D;
    for (int i = tid; i < 2048; i += 128) {           // coalesced float4
        float4 v = *(const float4*)&query[qbase + (size_t)i*4];
        int row = i >> 4, d4 = (i & 15) << 2;
        float* p = &sQ[row*SQ_STR + d4];
        p[0] = v.x; p[1] = v.y; p[2] = v.z; p[3] = v.w;
        uint2 h;                                      // emit fp16 Q copy
        h.x = h2u(v.x, v.y);
        h.y = h2u(v.z, v.w);
        *(uint2*)&g_qh[qbase + (size_t)i*4] = h;
    }
    for (int i = tid; i < 2048; i += 128) {           // fp16 V copy (fused)
        float4 v = *(const float4*)&value[qbase + (size_t)i*4];
        uint2 h;
        h.x = h2u(v.x, v.y);
        h.y = h2u(v.z, v.w);
        *(uint2*)&g_vh[qbase + (size_t)i*4] = h;
    }
    __syncthreads();

    const int t = blockIdx.x*128 + tid;
    const float* q = &sQ[tid*SQ_STR];

    unsigned long long acc2[32];
#pragma unroll
    for (int i = 0; i < 32; i++) acc2[i] = 0ULL;      // packed (0.f, 0.f)
    float nrm = 0.f;
    for (int d = 0; d < D; d++) {
        float qd = q[d];                              // conflict-free LDS
        nrm += qd*qd;
        unsigned long long q2;
        asm("mov.b64 %0, {%1, %1};" : "=l"(q2) : "f"(qd));
        const ulonglong2* rr = (const ulonglong2*)&sR[d*64];
#pragma unroll
        for (int i = 0; i < 16; i++) {
            ulonglong2 r2 = rr[i];                    // LDS.128 -> 2 b64 pairs
            asm("fma.rn.f32x2 %0, %1, %2, %0;" : "+l"(acc2[2*i])   : "l"(q2), "l"(r2.x));
            asm("fma.rn.f32x2 %0, %1, %2, %0;" : "+l"(acc2[2*i+1]) : "l"(q2), "l"(r2.y));
        }
    }
    g_qninv[b*S + t] = rsqrtf(fmaxf(nrm, 1e-12f));

    float acc[64];
#pragma unroll
    for (int i = 0; i < 32; i++) {
        float lo, hi;
        asm("mov.b64 {%0, %1}, %2;" : "=f"(lo), "=f"(hi) : "l"(acc2[i]));
        acc[2*i] = lo; acc[2*i+1] = hi;
    }

#pragma unroll
    for (int r = 0; r < R; r++) {
        float bv = acc[r*16];
        int   bi = 0;
#pragma unroll
        for (int k = 1; k < 16; k++) {
            float v = acc[r*16 + k];
            if (v > bv) { bv = v; bi = k; }
        }
#pragma unroll
        for (int k = 0; k < 16; k++) {
            float v = -acc[r*16 + k];
            if (v > bv) { bv = v; bi = 16 + k; }
        }
        g_bucket[(b*R + r)*S + t] = bi;
    }
}

// ---------------- kernel 2: stable counting sort per (b, r) --------------
// Scatter staged through smem; global writes fully coalesced int4.
__global__ void sort_kernel()
{
    __shared__ int hist[NB*256];   // bucket-major, thread-minor (32 KB)
    __shared__ int sidx_s[S];      // staged output (8 KB)
    __shared__ int wtot[8];
    const int br  = blockIdx.x;
    const int tid = threadIdx.x;
    const int* bk = g_bucket  + br*S;
    int*     sidx = g_sortidx + br*S;

    for (int i = tid; i < NB*256; i += 256) hist[i] = 0;
    __syncthreads();

    const int base = tid*8;
    int myb[8];
    {
        int4 b0 = *(const int4*)&bk[base];
        int4 b1 = *(const int4*)&bk[base + 4];
        myb[0]=b0.x; myb[1]=b0.y; myb[2]=b0.z; myb[3]=b0.w;
        myb[4]=b1.x; myb[5]=b1.y; myb[6]=b1.z; myb[7]=b1.w;
    }
#pragma unroll
    for (int k = 0; k < 8; k++) hist[myb[k]*256 + tid]++;
    __syncthreads();

    // exclusive scan over 8192 entries in index order (stable);
    // per-thread 32-entry chunk staged through registers
    int vals[32];
#pragma unroll
    for (int j = 0; j < 32; j++) vals[j] = hist[tid*32 + j];
    int run = 0;
#pragma unroll
    for (int j = 0; j < 32; j++) { int v = vals[j]; vals[j] = run; run += v; }
    const int lane = tid & 31, wid = tid >> 5;
    int x = run;
#pragma unroll
    for (int off = 1; off < 32; off <<= 1) {
        int nv = __shfl_up_sync(0xffffffffu, x, off);
        if (lane >= off) x += nv;
    }
    if (lane == 31) wtot[wid] = x;
    __syncthreads();
    if (tid < 8) {
        int y = wtot[tid], z = y;
#pragma unroll
        for (int off = 1; off < 8; off <<= 1) {
            int nv = __shfl_up_sync(0x000000ffu, z, off);
            if (tid >= off) z += nv;
        }
        wtot[tid] = z - y;    // exclusive warp offsets
    }
    __syncthreads();
    const int add = (x - run) + wtot[wid];
#pragma unroll
    for (int j = 0; j < 32; j++) hist[tid*32 + j] = vals[j] + add;
    __syncthreads();

#pragma unroll
    for (int k = 0; k < 8; k++) {
        int bb  = myb[k];
        int rnk = hist[bb*256 + tid]++;
        sidx_s[rnk] = base + k;         // scattered STS (cheap)
    }
    __syncthreads();
    for (int i = tid; i < S/4; i += 256)               // coalesced 16B stores
        *(int4*)&sidx[i*4] = *(const int4*)&sidx_s[i*4];
}

// ---------------- kernel 3: bucketed attention -----------------------------
// All-fp16 MMA; P lives in registers. Explicit per-key position masks.
// Tile stride 72 halves (144B = 9x16B, odd -> ldsm conflict-free) shrinks
// smem to 43 KB -> 5 CTAs/SM for better latency hiding.
// smem layout (bytes):
//   [0,2048)        kiS   : int[512]          window key positions, per round
//   [2048,4096)     cinvS : float[512]        1/duplicate-count
//   [4096,6144)     scS   : float[512]        per-key qn*0.125 scale
//   [6144,24576)    ksh   : half[128][72]     Q/K window tile (rows 64.. = Q)
//   [24576,43008)   vsh   : half[128][72]     V tile (cnt int[2048] aliases
//                                              during phase 0, before V0 load)
#define KSH_STR 72
#define VSH_STR 72
#define OFF_KI    0
#define OFF_CINV  2048
#define OFF_SC    4096
#define OFF_KS    6144
#define OFF_VS    24576
#define ATTN_SMEM 43008

__global__ void __launch_bounds__(128, 5) attn_kernel()
{
    extern __shared__ char smem[];
    int*    kiS   = (int*)   (smem + OFF_KI);
    float*  cinvS = (float*) (smem + OFF_CINV);
    float*  scS   = (float*) (smem + OFF_SC);
    int*    cnt   = (int*)   (smem + OFF_VS);   // alias (phase 0 only)

    const int blk = blockIdx.x;
    const int b   = blk >> 5;
    const int n   = blk & 31;
    const int tid = threadIdx.x;
    const int l   = tid & 31;
    const int mi  = tid >> 5;   // warp = m-tile (16 rows)

    const int* sidx_b = g_sortidx + b*R*S;
    const int  prev   = (n + 31) & 31;
    const float* qn   = g_qninv + b*S;
    const __half* Qh  = g_qh + (size_t)b*S*D;
    const __half* Vh  = g_vh + (size_t)b*S*D;

    const unsigned ks_s = (unsigned)__cvta_generic_to_shared(smem + OFF_KS);
    const unsigned vs_s = (unsigned)__cvta_generic_to_shared(smem + OFF_VS);
    const int i0 = mi*16 + (l>>2);

    // per-lane ldmatrix base addresses (bytes)
    const unsigned aG1 = ks_s + (unsigned)((64 + mi*16 + (l & 15))*KSH_STR)*2
                              + ((l >> 4) << 4);
    const unsigned bG1 = ks_s + (unsigned)(((l & 7) + ((l & 16) >> 1))*KSH_STR)*2
                              + (((l >> 3) & 1) << 4);
    const unsigned bG2 = vs_s + (unsigned)((l & 15)*VSH_STR)*2 + ((l >> 4) << 4);

    // ---- phase 0a: window key positions ----
    for (int idx = tid; idx < 512; idx += 128) {
        int r = idx >> 7, j = idx & 127;
        int slot = (j < 64) ? (prev*64 + j) : (n*64 + j - 64);
        kiS[idx] = sidx_b[r*S + slot];
    }
    __syncthreads();

    // ---- prologue: K0 load starts now (overlaps counting) ----
    {
        const int* ki = kiS;
#pragma unroll
        for (int it = 0; it < 8; it++) {         // 1024 x 16B
            int idx = it*128 + tid, row = idx >> 3, c8 = (idx & 7) << 3;
            cpa16(ks_s + (unsigned)row*(KSH_STR*2) + c8*2, &Qh[(size_t)ki[row]*D + c8]);
        }
        cpa_commit();
    }

    // ---- phase 0b: multiplicity counts + scales (cnt lives in vsh) ----
    for (int idx = tid; idx < 2048; idx += 128) cnt[idx] = 0;
    __syncthreads();
    for (int idx = tid; idx < 512; idx += 128) atomicAdd(&cnt[kiS[idx]], 1);
    __syncthreads();
    for (int idx = tid; idx < 512; idx += 128) {
        int kp = kiS[idx];
        cinvS[idx] = 1.f / (float)cnt[kp];
        scS[idx]   = qn[kp] * 0.125f;
    }
    __syncthreads();   // all cnt reads done; vsh free for V0

    // ---- prologue: V0 load ----
    {
        const int* ki = kiS;
#pragma unroll
        for (int it = 0; it < 8; it++) {
            int idx = it*128 + tid, row = idx >> 3, c8 = (idx & 7) << 3;
            cpa16(vs_s + (unsigned)row*(VSH_STR*2) + c8*2, &Vh[(size_t)ki[row]*D + c8]);
        }
        cpa_commit();
    }

    for (int r = 0; r < R; r++) {
        const int* ki = kiS + r*128;

        // ---- K(r) ready (oldest outstanding group) ----
        cpa_wait1();
        __syncthreads();

        // ---- GEMM1 (fp16): S[16x128] per warp = Q(rows 64..127) . K^T ----
        float acc[16][4];
#pragma unroll
        for (int t2 = 0; t2 < 16; t2++)
#pragma unroll
            for (int c = 0; c < 4; c++) acc[t2][c] = 0.f;

        unsigned af[4][4];                           // A frags, 4 k16 chunks
#pragma unroll
        for (int c = 0; c < 4; c++)
            ldsm4(af[c][0], af[c][1], af[c][2], af[c][3], aG1 + c*32);

#pragma unroll
        for (int p = 0; p < 8; p++) {                // n-tile pairs 2p, 2p+1
#pragma unroll
            for (int c = 0; c < 4; c++) {            // k16 chunks
                unsigned b0,b1,b2,b3;
                ldsm4(b0,b1,b2,b3, bG1 + (unsigned)(p*16*KSH_STR)*2 + c*32);
                mma_f16(acc[2*p],   af[c], b0, b1);
                mma_f16(acc[2*p+1], af[c], b2, b3);
            }
        }
        __syncthreads();   // all warps' ksh reads done

        // ---- prefetch K(r+1) into ksh (overlaps softmax + GEMM2) ----
        if (r < R-1) {
            const int* kin = kiS + (r+1)*128;
#pragma unroll
            for (int it = 0; it < 8; it++) {
                int idx = it*128 + tid, row = idx >> 3, c8 = (idx & 7) << 3;
                cpa16(ks_s + (unsigned)row*(KSH_STR*2) + c8*2, &Qh[(size_t)kin[row]*D + c8]);
            }
            cpa_commit();
        }

        // ---- in-register scale + masks + softmax (single warp per row) --
        const int qpos0 = ki[64 + i0];
        const int qpos1 = ki[64 + i0 + 8];
        float m0 = -3.4e38f, m1 = -3.4e38f;
#pragma unroll
        for (int nt = 0; nt < 16; nt++) {
#pragma unroll
            for (int e = 0; e < 2; e++) {
                int col = nt*8 + 2*(l&3) + e;
                int kp  = ki[col];
                float sc = scS[r*128 + col];
                float x = acc[nt][e] * sc;
                if      (qpos0 <  kp) x = -1.0e9f;
                else if (qpos0 == kp) x = -1.0e5f;
                acc[nt][e] = x; m0 = fmaxf(m0, x);
                float y = acc[nt][2+e] * sc;
                if      (qpos1 <  kp) y = -1.0e9f;
                else if (qpos1 == kp) y = -1.0e5f;
                acc[nt][2+e] = y; m1 = fmaxf(m1, y);
            }
        }
        m0 = fmaxf(m0, __shfl_xor_sync(0xffffffffu, m0, 1));
        m0 = fmaxf(m0, __shfl_xor_sync(0xffffffffu, m0, 2));
        m1 = fmaxf(m1, __shfl_xor_sync(0xffffffffu, m1, 1));
        m1 = fmaxf(m1, __shfl_xor_sync(0xffffffffu, m1, 2));
        float s0 = 0.f, s1 = 0.f;
#pragma unroll
        for (int nt = 0; nt < 16; nt++)
#pragma unroll
            for (int e = 0; e < 2; e++) {
                float ex = __expf(acc[nt][e]   - m0); acc[nt][e]   = ex; s0 += ex;
                float ey = __expf(acc[nt][2+e] - m1); acc[nt][2+e] = ey; s1 += ey;
            }
        s0 += __shfl_xor_sync(0xffffffffu, s0, 1);
        s0 += __shfl_xor_sync(0xffffffffu, s0, 2);
        s1 += __shfl_xor_sync(0xffffffffu, s1, 1);
        s1 += __shfl_xor_sync(0xffffffffu, s1, 2);
        const float f0 = 1.f / s0;
        const float f1 = 1.f / s1;

        // ---- pack P into fp16 A-fragments (8 k16 chunks; no smem) ----
        unsigned ra[8][4];
#pragma unroll
        for (int t = 0; t < 8; t++) {
            int col0 = 16*t + 2*(l&3);
            float2 ci = *(float2*)&cinvS[r*128 + col0];
            float2 cj = *(float2*)&cinvS[r*128 + col0 + 8];
            ra[t][0] = h2u(acc[2*t][0]*f0*ci.x,   acc[2*t][1]*f0*ci.y);
            ra[t][1] = h2u(acc[2*t][2]*f1*ci.x,   acc[2*t][3]*f1*ci.y);
            ra[t][2] = h2u(acc[2*t+1][0]*f0*cj.x, acc[2*t+1][1]*f0*cj.y);
            ra[t][3] = h2u(acc[2*t+1][2]*f1*cj.x, acc[2*t+1][3]*f1*cj.y);
        }
        if ((l & 3) == 0) {
            g_lse[((size_t)b*S + qpos0)*R + r] = m0 + __logf(s0);
            g_lse[((size_t)b*S + qpos1)*R + r] = m1 + __logf(s1);
        }

        // ---- V(r) ready ----
        if (r < R-1) cpa_wait1(); else cpa_wait0();
        __syncthreads();

        // ---- GEMM2 (fp16): full 128-key k per warp, all 64 dims ----
        float acc2[8][4];
#pragma unroll
        for (int t2 = 0; t2 < 8; t2++)
#pragma unroll
            for (int c = 0; c < 4; c++) acc2[t2][c] = 0.f;

#pragma unroll
        for (int t = 0; t < 8; t++) {              // k16 chunks over 128 keys
#pragma unroll
            for (int p = 0; p < 4; p++) {          // dim tiles 2p, 2p+1
                unsigned b0,b1,b2,b3;
                ldsm4t(b0,b1,b2,b3, bG2 + (unsigned)(t*16*VSH_STR)*2 + p*32);
                mma_f16(acc2[2*p],   ra[t], b0, b1);
                mma_f16(acc2[2*p+1], ra[t], b2, b3);
            }
        }

        __half* o0 = g_att + (((size_t)b*S + qpos0)*R + r)*D;
        __half* o1 = g_att + (((size_t)b*S + qpos1)*R + r)*D;
#pragma unroll
        for (int j = 0; j < 8; j++) {
            int c0 = j*8 + 2*(l&3);
            *(__half2*)&o0[c0] = __floats2half2_rn(acc2[j][0], acc2[j][1]);
            *(__half2*)&o1[c0] = __floats2half2_rn(acc2[j][2], acc2[j][3]);
        }
        __syncthreads();   // all vsh reads done

        // ---- prefetch V(r+1) into vsh (overlaps next round's GEMM1) ----
        if (r < R-1) {
            const int* kin = kiS + (r+1)*128;
#pragma unroll
            for (int it = 0; it < 8; it++) {
                int idx = it*128 + tid, row = idx >> 3, c8 = (idx & 7) << 3;
                cpa16(vs_s + (unsigned)row*(VSH_STR*2) + c8*2, &Vh[(size_t)kin[row]*D + c8]);
            }
            cpa_commit();
        }
    }
}

// ---------------- kernel 4: round combine, 8 threads/row, 2 rows/thread --
__global__ void __launch_bounds__(256) combine_kernel(float* __restrict__ out)
{
    const int tid  = threadIdx.x;
    const int j    = tid & 7;                       // dim octet within row
    const int rowA = blockIdx.x*64 + (tid >> 3);    // b*S + t
    const int rowB = rowA + 32;

    float4 lvA = *(const float4*)(g_lse + (size_t)rowA*R);
    float4 lvB = *(const float4*)(g_lse + (size_t)rowB*R);

    const __half* aA = g_att + ((size_t)rowA*R)*D + j*8;
    const __half* aB = g_att + ((size_t)rowB*R)*D + j*8;
    uint4 qA0 = *(const uint4*)(aA);
    uint4 qA1 = *(const uint4*)(aA + D);
    uint4 qA2 = *(const uint4*)(aA + 2*D);
    uint4 qA3 = *(const uint4*)(aA + 3*D);
    uint4 qB0 = *(const uint4*)(aB);
    uint4 qB1 = *(const uint4*)(aB + D);
    uint4 qB2 = *(const uint4*)(aB + 2*D);
    uint4 qB3 = *(const uint4*)(aB + 3*D);

    {
        float m  = fmaxf(fmaxf(lvA.x, lvA.y), fmaxf(lvA.z, lvA.w));
        float w0 = __expf(lvA.x - m), w1 = __expf(lvA.y - m);
        float w2 = __expf(lvA.z - m), w3 = __expf(lvA.w - m);
        float inv = 1.f / (w0 + w1 + w2 + w3);
        const __half2* h0 = (const __half2*)&qA0;
        const __half2* h1 = (const __half2*)&qA1;
        const __half2* h2 = (const __half2*)&qA2;
        const __half2* h3 = (const __half2*)&qA3;
        float res[8];
#pragma unroll
        for (int k = 0; k < 4; k++) {
            float2 a0 = __half22float2(h0[k]);
            float2 a1 = __half22float2(h1[k]);
            float2 a2 = __half22float2(h2[k]);
            float2 a3 = __half22float2(h3[k]);
            res[2*k]   = (a0.x*w0 + a1.x*w1 + a2.x*w2 + a3.x*w3) * inv;
            res[2*k+1] = (a0.y*w0 + a1.y*w1 + a2.y*w2 + a3.y*w3) * inv;
        }
        float* o = &out[(size_t)rowA*D + j*8];
        *(float4*)o       = make_float4(res[0], res[1], res[2], res[3]);
        *(float4*)(o + 4) = make_float4(res[4], res[5], res[6], res[7]);
    }
    {
        float m  = fmaxf(fmaxf(lvB.x, lvB.y), fmaxf(lvB.z, lvB.w));
        float w0 = __expf(lvB.x - m), w1 = __expf(lvB.y - m);
        float w2 = __expf(lvB.z - m), w3 = __expf(lvB.w - m);
        float inv = 1.f / (w0 + w1 + w2 + w3);
        const __half2* h0 = (const __half2*)&qB0;
        const __half2* h1 = (const __half2*)&qB1;
        const __half2* h2 = (const __half2*)&qB2;
        const __half2* h3 = (const __half2*)&qB3;
        float res[8];
#pragma unroll
        for (int k = 0; k < 4; k++) {
            float2 a0 = __half22float2(h0[k]);
            float2 a1 = __half22float2(h1[k]);
            float2 a2 = __half22float2(h2[k]);
            float2 a3 = __half22float2(h3[k]);
            res[2*k]   = (a0.x*w0 + a1.x*w1 + a2.x*w2 + a3.x*w3) * inv;
            res[2*k+1] = (a0.y*w0 + a1.y*w1 + a2.y*w2 + a3.y*w3) * inv;
        }
        float* o = &out[(size_t)rowB*D + j*8];
        *(float4*)o       = make_float4(res[0], res[1], res[2], res[3]);
        *(float4*)(o + 4) = make_float4(res[4], res[5], res[6], res[7]);
    }
}

// ---------------- launch --------------------------------------------------
extern "C" void kernel_launch(void* const* d_in, const int* in_sizes, int n_in,
                              void* d_out, int out_size)
{
    const float* query = (const float*)d_in[0];
    const float* value = (const float*)d_in[1];
    const float* randm = (const float*)d_in[2];
    float* out = (float*)d_out;

    cudaFuncSetAttribute(hash_kernel,
                         cudaFuncAttributeMaxDynamicSharedMemorySize, HASH_SMEM);
    cudaFuncSetAttribute(attn_kernel,
                         cudaFuncAttributeMaxDynamicSharedMemorySize, ATTN_SMEM);

    hash_kernel<<<dim3(S/128, B), 128, HASH_SMEM>>>(query, value, randm);
    sort_kernel<<<B*R, 256>>>();
    attn_kernel<<<B*NB, 128, ATTN_SMEM>>>();
    combine_kernel<<<(B*S)/64, 256>>>(out);
}